// round 6
// baseline (speedup 1.0000x reference)
#include <cuda_runtime.h>
#include <cstdint>
#include <cstddef>

#define DIMC 256
#define NH 8
#define HD 32
#define NQ 4096
#define NU 1024
#define BATCH 2

// 1 = JAX threefry_partitionable (default in jax >= 0.5): bits = o0^o1, counts (hi=0, lo=j)
// 0 = legacy path: counts (j, j+8192) -> o0 for j<8192, (j-8192, j) -> o1 otherwise
#define THREEFRY_PARTITIONABLE 1

// ---------------- scratch (device globals; no allocation) ----------------
__device__ float g_q   [BATCH * DIMC * NQ];      // q channels  [b][c][n], c = h*32+d
__device__ float g_kvu [BATCH * 2 * DIMC * NU];  // kv upper    [b][c][m], head h: k=c in [h*64,h*64+32), v next 32
__device__ float g_fkv [BATCH * 2 * DIMC * NQ];  // fine kv     [b][c][n]
__device__ float g_qm  [BATCH * DIMC];           // mean over n of q
__device__ float g_gs  [BATCH * NH * NU];        // global scores + gumbel
__device__ int   g_idx [BATCH * NH * 16];        // expanded topk indices
__device__ float g_out [BATCH * DIMC * NQ];      // gated attention output (channel layout)
__device__ float g_vpe [BATCH * DIMC * NU];      // depthwise conv result (32x32)

// ---------------- fast exp2 (all-FFMA, no MUFU) ----------------
__device__ __forceinline__ float fexp2(float x) {
    x = fmaxf(fminf(x, 126.0f), -120.0f);
    float z = x + 12582912.0f;               // 1.5 * 2^23
    int   e = __float_as_int(z) - 0x4B400000; // round(x)
    float f = x - (z - 12582912.0f);          // in [-0.5, 0.5]
    float p = fmaf(f, 1.3333558146e-3f, 9.6181291918e-3f);
    p = fmaf(f, p, 5.5504108664e-2f);
    p = fmaf(f, p, 2.4022650696e-1f);
    p = fmaf(f, p, 6.9314718056e-1f);
    p = fmaf(f, p, 1.0f);
    return p * __int_as_float((e + 127) << 23);
}

// ---------------- threefry2x32 (key = (0, 42)) ----------------
__device__ __forceinline__ uint32_t rotl32(uint32_t v, int n) { return (v << n) | (v >> (32 - n)); }

__device__ __forceinline__ void tf2x32(uint32_t c0, uint32_t c1, uint32_t& o0, uint32_t& o1) {
    const uint32_t k0 = 0u, k1 = 42u, k2 = 0u ^ 42u ^ 0x1BD11BDAu;
    uint32_t x0 = c0 + k0, x1 = c1 + k1;
#define TFR(r) { x0 += x1; x1 = rotl32(x1, r); x1 ^= x0; }
    TFR(13) TFR(15) TFR(26) TFR(6)
    x0 += k1; x1 += k2 + 1u;
    TFR(17) TFR(29) TFR(16) TFR(24)
    x0 += k2; x1 += k0 + 2u;
    TFR(13) TFR(15) TFR(26) TFR(6)
    x0 += k0; x1 += k1 + 3u;
    TFR(17) TFR(29) TFR(16) TFR(24)
    x0 += k1; x1 += k2 + 4u;
    TFR(13) TFR(15) TFR(26) TFR(6)
    x0 += k2; x1 += k0 + 5u;
#undef TFR
    o0 = x0; o1 = x1;
}

// ---------------- GEMM: C[M,N] = W[M,256] @ X[256,N] + bias, batched over z ----------------
__global__ __launch_bounds__(256) void gemm128(const float* __restrict__ W,
                                               const float* __restrict__ X,
                                               const float* __restrict__ bias,
                                               float* __restrict__ C, int M, int N) {
    const int K = DIMC;
    int b = blockIdx.z;
    X += (size_t)b * K * N;
    C += (size_t)b * M * N;
    __shared__ float Ws[8][132];
    __shared__ float Xs[8][128];
    int tid = threadIdx.x;
    int tx = tid & 15, ty = tid >> 4;
    int bm = blockIdx.y * 128, bn = blockIdx.x * 128;
    float acc[8][8];
#pragma unroll
    for (int i = 0; i < 8; i++)
#pragma unroll
        for (int j = 0; j < 8; j++) acc[i][j] = 0.f;

    int wk = tid & 7, wm = tid >> 3;     // W tile: k fast
    int xk = tid >> 7, xn = tid & 127;   // X tile: n fast

    for (int k0 = 0; k0 < K; k0 += 8) {
#pragma unroll
        for (int p = 0; p < 4; p++)
            Ws[wk][wm + p * 32] = W[(size_t)(bm + wm + p * 32) * K + k0 + wk];
#pragma unroll
        for (int p = 0; p < 4; p++)
            Xs[xk + p * 2][xn] = X[(size_t)(k0 + xk + p * 2) * N + bn + xn];
        __syncthreads();
#pragma unroll
        for (int k = 0; k < 8; k++) {
            float a[8], bb[8];
            *(float4*)&a[0]  = *(const float4*)&Ws[k][ty * 4];
            *(float4*)&a[4]  = *(const float4*)&Ws[k][64 + ty * 4];
            *(float4*)&bb[0] = *(const float4*)&Xs[k][tx * 4];
            *(float4*)&bb[4] = *(const float4*)&Xs[k][64 + tx * 4];
#pragma unroll
            for (int i = 0; i < 8; i++)
#pragma unroll
                for (int j = 0; j < 8; j++) acc[i][j] = fmaf(a[i], bb[j], acc[i][j]);
        }
        __syncthreads();
    }
#pragma unroll
    for (int i = 0; i < 8; i++) {
        int m = bm + ((i < 4) ? (ty * 4 + i) : (64 + ty * 4 + (i - 4)));
        float bv = bias[m];
        float4 v0 = make_float4(acc[i][0] + bv, acc[i][1] + bv, acc[i][2] + bv, acc[i][3] + bv);
        float4 v1 = make_float4(acc[i][4] + bv, acc[i][5] + bv, acc[i][6] + bv, acc[i][7] + bv);
        *(float4*)&C[(size_t)m * N + bn + tx * 4]      = v0;
        *(float4*)&C[(size_t)m * N + bn + 64 + tx * 4] = v1;
    }
}

// ---------------- mean over n of q channels ----------------
__global__ void qmean_k() {
    int b = blockIdx.x >> 8, c = blockIdx.x & 255;
    const float* p = g_q + ((size_t)b * DIMC + c) * NQ;
    float s = 0.f;
    for (int n = threadIdx.x; n < NQ; n += 128) s += p[n];
    __shared__ float sh[4];
    for (int o = 16; o; o >>= 1) s += __shfl_down_sync(0xffffffffu, s, o);
    if ((threadIdx.x & 31) == 0) sh[threadIdx.x >> 5] = s;
    __syncthreads();
    if (threadIdx.x == 0)
        g_qm[b * DIMC + c] = (sh[0] + sh[1] + sh[2] + sh[3]) * (1.0f / NQ);
}

// ---------------- global scores + gumbel ----------------
__global__ void gs_k() {
    int j = blockIdx.x * 128 + threadIdx.x;   // 0..16383 == flat (2,8,1024)
    int b = j >> 13, r = j & 8191, h = r >> 10, m = r & 1023;
    const float* qm = g_qm + b * DIMC + h * HD;
    const float* kc = g_kvu + ((size_t)b * 512 + h * 64) * NU + m;
    float s = 0.f;
#pragma unroll
    for (int d = 0; d < 32; d++) s = fmaf(qm[d], kc[(size_t)d * NU], s);

    uint32_t bits;
#if THREEFRY_PARTITIONABLE
    { uint32_t o0, o1; tf2x32(0u, (uint32_t)j, o0, o1); bits = o0 ^ o1; }
#else
    { uint32_t o0, o1;
      if (j < 8192) { tf2x32((uint32_t)j, (uint32_t)(j + 8192), o0, o1); bits = o0; }
      else          { tf2x32((uint32_t)(j - 8192), (uint32_t)j, o0, o1); bits = o1; } }
#endif
    float f = __uint_as_float((bits >> 9) | 0x3f800000u) - 1.0f;
    const float TINY = 1.1754943508222875e-38f;
    float u = fmaxf(TINY, f + TINY);
    float gum = -logf(-logf(u));
    g_gs[j] = s * 0.17677669529663687f + gum;
}

// ---------------- top-4 per (b,h) + 2x2 expansion ----------------
__global__ void topk_k() {
    int bh = blockIdx.x;
    __shared__ float sv[NU];
    __shared__ float rv[256];
    __shared__ int   ri[256];
    __shared__ int   chosen[4];
    int t = threadIdx.x;
    for (int i = t; i < NU; i += 256) sv[i] = g_gs[bh * NU + i];
    __syncthreads();
    for (int rnd = 0; rnd < 4; rnd++) {
        float bestv = -1e30f; int besti = NU;
        for (int i = t; i < NU; i += 256) {
            float v = sv[i];
            if (v > bestv) { bestv = v; besti = i; }
        }
        rv[t] = bestv; ri[t] = besti;
        __syncthreads();
        for (int o = 128; o; o >>= 1) {
            if (t < o) {
                float v2 = rv[t + o]; int i2 = ri[t + o];
                if (v2 > rv[t] || (v2 == rv[t] && i2 < ri[t])) { rv[t] = v2; ri[t] = i2; }
            }
            __syncthreads();
        }
        if (t == 0) { chosen[rnd] = ri[0]; sv[ri[0]] = -1e30f; }
        __syncthreads();
    }
    if (t < 16) {
        int g = t >> 2, kk = t & 3;
        int dh = g >> 1, dw = g & 1;
        int ti = chosen[kk];
        int hi = (ti >> 5) * 2, wi = (ti & 31) * 2;
        g_idx[bh * 16 + t] = (hi + dh) * 64 + (wi + dw);
    }
}

// ---------------- fused coarse + fine attention + gate ----------------
__global__ __launch_bounds__(128) void attn_k(const float* __restrict__ Wg,
                                              const float* __restrict__ bg) {
    __shared__ float Ksh[32][64];
    __shared__ float Vsh[32][64];
    __shared__ float FK[16][32];
    __shared__ float FV[16][32];
    __shared__ float Wgs[32][64];
    __shared__ float bgs[32];

    int bh = blockIdx.y, b = bh >> 3, h = bh & 7;
    int t = threadIdx.x;
    int n = blockIdx.x * 128 + t;

    for (int e = t; e < 2048; e += 128) Wgs[e >> 6][e & 63] = Wg[e];
    if (t < 32) bgs[t] = bg[t];
    {
        const int* idxp = g_idx + bh * 16;
        for (int e = t; e < 512; e += 128) {
            int j = e >> 5, d = e & 31;
            int nn = idxp[j];
            FK[j][d] = g_fkv[((size_t)b * 512 + h * 64 + d) * NQ + nn];
            FV[j][d] = g_fkv[((size_t)b * 512 + h * 64 + 32 + d) * NQ + nn];
        }
    }

    float q[32];
    const float* qbase = g_q + ((size_t)b * DIMC + h * HD) * NQ + n;
#pragma unroll
    for (int d = 0; d < 32; d++) q[d] = qbase[(size_t)d * NQ];

    float acc[32];
#pragma unroll
    for (int d = 0; d < 32; d++) acc[d] = 0.f;
    float ssum = 0.f;
    const float SCL = 0.17677669529663687f * 1.4426950408889634f;  // hd^-.5 * log2(e)

    const float* kbase = g_kvu + ((size_t)b * 512 + h * 64) * NU;
    const float* vbase = kbase + (size_t)32 * NU;

    for (int m0 = 0; m0 < NU; m0 += 64) {
        __syncthreads();
        for (int e = t; e < 2048; e += 128) {
            int d = e >> 6, m = e & 63;
            Ksh[d][m] = kbase[(size_t)d * NU + m0 + m];
            Vsh[d][m] = vbase[(size_t)d * NU + m0 + m];
        }
        __syncthreads();
#pragma unroll 2
        for (int m = 0; m < 64; m++) {
            float s0 = 0.f, s1 = 0.f;
#pragma unroll
            for (int d = 0; d < 32; d += 2) {
                s0 = fmaf(q[d],     Ksh[d][m],     s0);
                s1 = fmaf(q[d + 1], Ksh[d + 1][m], s1);
            }
            float e1 = fexp2((s0 + s1) * SCL);
            ssum += e1;
#pragma unroll
            for (int d = 0; d < 32; d++) acc[d] = fmaf(e1, Vsh[d][m], acc[d]);
        }
    }

    // fine attention over 16 gathered keys
    float fw[16]; float fsum = 0.f;
#pragma unroll
    for (int j = 0; j < 16; j++) {
        float s = 0.f;
#pragma unroll
        for (int d = 0; d < 32; d++) s = fmaf(q[d], FK[j][d], s);
        float e1 = fexp2(s * SCL);
        fw[j] = e1; fsum += e1;
    }
    float inv_f = 1.0f / fsum;
    float inv_c = 1.0f / ssum;

    // refined into q regs (q no longer needed), coarse in acc
#pragma unroll
    for (int d = 0; d < 32; d++) {
        float r = 0.f;
#pragma unroll
        for (int j = 0; j < 16; j++) r = fmaf(fw[j], FV[j][d], r);
        q[d]   = r * inv_f;
        acc[d] = acc[d] * inv_c;
    }

    float* outb = g_out + ((size_t)b * DIMC + h * HD) * NQ + n;
#pragma unroll
    for (int d = 0; d < 32; d++) {
        float s = bgs[d];
#pragma unroll
        for (int c = 0; c < 32; c++) s = fmaf(acc[c], Wgs[d][c], s);
#pragma unroll
        for (int c = 0; c < 32; c++) s = fmaf(q[c], Wgs[d][32 + c], s);
        float gate = 1.0f / (1.0f + fexp2(-s * 1.4426950408889634f));
        outb[(size_t)d * NQ] = acc[d] + gate * (q[d] - acc[d]);
    }
}

// ---------------- depthwise 7x7 conv on v (32x32 grid) ----------------
__global__ void pe_conv_k(const float* __restrict__ Wpe, const float* __restrict__ bpe) {
    int gid = blockIdx.x * 128 + threadIdx.x;     // < 2*256*1024
    int p = gid & 1023, c = (gid >> 10) & 255, b = gid >> 18;
    int y = p >> 5, x = p & 31;
    int h = c >> 5, d = c & 31;
    const float* vsrc = g_kvu + ((size_t)b * 512 + h * 64 + 32 + d) * NU;
    const float* w = Wpe + c * 49;
    float s = bpe[c];
#pragma unroll
    for (int ky = 0; ky < 7; ky++) {
        int iy = y + ky - 3;
        if ((unsigned)iy < 32u) {
#pragma unroll
            for (int kx = 0; kx < 7; kx++) {
                int ix = x + kx - 3;
                if ((unsigned)ix < 32u) s = fmaf(vsrc[iy * 32 + ix], w[ky * 7 + kx], s);
            }
        }
    }
    g_vpe[gid] = s;
}

// ---------------- bilinear 2x upsample (half-pixel, edge-normalized) + add ----------------
__global__ void upadd_k() {
    int gid = blockIdx.x * 256 + threadIdx.x;     // < 2*256*4096
    int n = gid & 4095, c = (gid >> 12) & 255, b = gid >> 20;
    int y = n >> 6, x = n & 63;
    float fy = (y + 0.5f) * 0.5f - 0.5f;
    float fx = (x + 0.5f) * 0.5f - 0.5f;
    float yf = floorf(fy), xf = floorf(fx);
    float ty = fy - yf, tx = fx - xf;
    int y0 = max(0, min(31, (int)yf)),     y1 = max(0, min(31, (int)yf + 1));
    int x0 = max(0, min(31, (int)xf)),     x1 = max(0, min(31, (int)xf + 1));
    const float* src = g_vpe + ((size_t)b * 256 + c) * NU;
    float v = (1.f - ty) * ((1.f - tx) * src[y0 * 32 + x0] + tx * src[y0 * 32 + x1])
            +        ty  * ((1.f - tx) * src[y1 * 32 + x0] + tx * src[y1 * 32 + x1]);
    g_out[gid] += v;
}

// ---------------- launch ----------------
extern "C" void kernel_launch(void* const* d_in, const int* in_sizes, int n_in,
                              void* d_out, int out_size) {
    const float* x     = (const float*)d_in[0];
    const float* uf    = (const float*)d_in[1];
    const float* Wq    = (const float*)d_in[2];
    const float* bq    = (const float*)d_in[3];
    const float* Wkv   = (const float*)d_in[4];
    const float* bkv   = (const float*)d_in[5];
    const float* Wproj = (const float*)d_in[6];
    const float* bproj = (const float*)d_in[7];
    const float* Wpe   = (const float*)d_in[8];
    const float* bpe   = (const float*)d_in[9];
    const float* Wg    = (const float*)d_in[10];
    const float* bg    = (const float*)d_in[11];
    float* out = (float*)d_out;

    float *pq, *pkvu, *pfkv, *pout;
    cudaGetSymbolAddress((void**)&pq,   g_q);
    cudaGetSymbolAddress((void**)&pkvu, g_kvu);
    cudaGetSymbolAddress((void**)&pfkv, g_fkv);
    cudaGetSymbolAddress((void**)&pout, g_out);

    gemm128<<<dim3(32, 2, 2), 256>>>(Wq,  x,  bq,  pq,   256, 4096);
    gemm128<<<dim3(8,  4, 2), 256>>>(Wkv, uf, bkv, pkvu, 512, 1024);
    gemm128<<<dim3(32, 4, 2), 256>>>(Wkv, x,  bkv, pfkv, 512, 4096);
    qmean_k<<<512, 128>>>();
    gs_k<<<128, 128>>>();
    topk_k<<<16, 256>>>();
    attn_k<<<dim3(32, 16), 128>>>(Wg, bg);
    pe_conv_k<<<4096, 128>>>(Wpe, bpe);
    upadd_k<<<8192, 256>>>();
    gemm128<<<dim3(32, 2, 2), 256>>>(Wproj, pout, bproj, out, 256, 4096);
}

// round 9
// speedup vs baseline: 1.1306x; 1.1306x over previous
#include <cuda_runtime.h>
#include <cstdint>
#include <cstddef>

#define DIMC 256
#define NH 8
#define HD 32
#define NQ 4096
#define NU 1024
#define BATCH 2

#define THREEFRY_PARTITIONABLE 1

typedef unsigned long long ull;

// ---------------- scratch (device globals; no allocation) ----------------
__device__ float g_q   [BATCH * DIMC * NQ];      // q channels  [b][c][n]
__device__ float g_kvu [BATCH * 2 * DIMC * NU];  // kv upper    [b][c][m]
__device__ float g_fkv [BATCH * 2 * DIMC * NQ];  // fine kv     [b][c][n]
__device__ float g_qm  [BATCH * DIMC];
__device__ float g_gs  [BATCH * NH * NU];
__device__ int   g_idx [BATCH * NH * 16];
__device__ float g_out [BATCH * DIMC * NQ];
__device__ float g_vpe [BATCH * DIMC * NU];

// ---------------- f32x2 packed helpers ----------------
__device__ __forceinline__ ull ffma2(ull a, ull b, ull c) {
    ull d; asm("fma.rn.f32x2 %0, %1, %2, %3;" : "=l"(d) : "l"(a), "l"(b), "l"(c)); return d;
}
__device__ __forceinline__ ull fmul2(ull a, ull b) {
    ull d; asm("mul.rn.f32x2 %0, %1, %2;" : "=l"(d) : "l"(a), "l"(b)); return d;
}
__device__ __forceinline__ ull pack2(float lo, float hi) {
    ull r; asm("mov.b64 %0, {%1, %2};" : "=l"(r) : "f"(lo), "f"(hi)); return r;
}
__device__ __forceinline__ float2 unpack2(ull v) {
    float2 f; asm("mov.b64 {%0, %1}, %2;" : "=f"(f.x), "=f"(f.y) : "l"(v)); return f;
}

// ---------------- fast exp2 (scalar, clamped) ----------------
__device__ __forceinline__ float fexp2(float x) {
    x = fmaxf(fminf(x, 126.0f), -120.0f);
    float z = x + 12582912.0f;
    int   e = __float_as_int(z) - 0x4B400000;
    float f = x - (z - 12582912.0f);
    float p = fmaf(f, 1.3333558146e-3f, 9.6181291918e-3f);
    p = fmaf(f, p, 5.5504108664e-2f);
    p = fmaf(f, p, 2.4022650696e-1f);
    p = fmaf(f, p, 6.9314718056e-1f);
    p = fmaf(f, p, 1.0f);
    return p * __int_as_float((e + 127) << 23);
}

// packed exp2 of two scores (inputs bounded, no clamp needed)
__device__ __forceinline__ ull fexp2_2(float x0, float x1) {
    float z0 = x0 + 12582912.0f, z1 = x1 + 12582912.0f;
    int e0 = __float_as_int(z0) - 0x4B400000;
    int e1 = __float_as_int(z1) - 0x4B400000;
    float f0 = x0 - (z0 - 12582912.0f);
    float f1 = x1 - (z1 - 12582912.0f);
    ull f2 = pack2(f0, f1);
    ull p  = pack2(1.3333558146e-3f, 1.3333558146e-3f);
    p = ffma2(f2, p, pack2(9.6181291918e-3f, 9.6181291918e-3f));
    p = ffma2(f2, p, pack2(5.5504108664e-2f, 5.5504108664e-2f));
    p = ffma2(f2, p, pack2(2.4022650696e-1f, 2.4022650696e-1f));
    p = ffma2(f2, p, pack2(6.9314718056e-1f, 6.9314718056e-1f));
    p = ffma2(f2, p, pack2(1.0f, 1.0f));
    ull sc = pack2(__int_as_float((e0 + 127) << 23), __int_as_float((e1 + 127) << 23));
    return fmul2(p, sc);
}

// ---------------- threefry2x32 (key = (0, 42)) ----------------
__device__ __forceinline__ uint32_t rotl32(uint32_t v, int n) { return (v << n) | (v >> (32 - n)); }

__device__ __forceinline__ void tf2x32(uint32_t c0, uint32_t c1, uint32_t& o0, uint32_t& o1) {
    const uint32_t k0 = 0u, k1 = 42u, k2 = 0u ^ 42u ^ 0x1BD11BDAu;
    uint32_t x0 = c0 + k0, x1 = c1 + k1;
#define TFR(r) { x0 += x1; x1 = rotl32(x1, r); x1 ^= x0; }
    TFR(13) TFR(15) TFR(26) TFR(6)
    x0 += k1; x1 += k2 + 1u;
    TFR(17) TFR(29) TFR(16) TFR(24)
    x0 += k2; x1 += k0 + 2u;
    TFR(13) TFR(15) TFR(26) TFR(6)
    x0 += k0; x1 += k1 + 3u;
    TFR(17) TFR(29) TFR(16) TFR(24)
    x0 += k1; x1 += k2 + 4u;
    TFR(13) TFR(15) TFR(26) TFR(6)
    x0 += k2; x1 += k0 + 5u;
#undef TFR
    o0 = x0; o1 = x1;
}

// ---------------- GEMM (f32x2): C[M,N] = W[M,256] @ X[256,N] + bias ----------------
__global__ __launch_bounds__(256) void gemm128(const float* __restrict__ W,
                                               const float* __restrict__ X,
                                               const float* __restrict__ bias,
                                               float* __restrict__ C, int M, int N) {
    const int K = DIMC;
    int b = blockIdx.z;
    X += (size_t)b * K * N;
    C += (size_t)b * M * N;
    __shared__ float Ws[8][132];
    __shared__ float Xs[8][128];
    int tid = threadIdx.x;
    int tx = tid & 15, ty = tid >> 4;
    int bm = blockIdx.y * 128, bn = blockIdx.x * 128;

    ull acc2[4][8];
#pragma unroll
    for (int i = 0; i < 4; i++)
#pragma unroll
        for (int j = 0; j < 8; j++) acc2[i][j] = 0ull;

    int wk = tid & 7, wm = tid >> 3;
    int xk = tid >> 7, xn = tid & 127;

    for (int k0 = 0; k0 < K; k0 += 8) {
#pragma unroll
        for (int p = 0; p < 4; p++)
            Ws[wk][wm + p * 32] = W[(size_t)(bm + wm + p * 32) * K + k0 + wk];
#pragma unroll
        for (int p = 0; p < 4; p++)
            Xs[xk + p * 2][xn] = X[(size_t)(k0 + xk + p * 2) * N + bn + xn];
        __syncthreads();
#pragma unroll
        for (int k = 0; k < 8; k++) {
            ull a2[4];
            {
                ulonglong2 t0 = *(const ulonglong2*)&Ws[k][ty * 4];
                ulonglong2 t1 = *(const ulonglong2*)&Ws[k][64 + ty * 4];
                a2[0] = t0.x; a2[1] = t0.y; a2[2] = t1.x; a2[3] = t1.y;
            }
            float bb[8];
            *(float4*)&bb[0] = *(const float4*)&Xs[k][tx * 4];
            *(float4*)&bb[4] = *(const float4*)&Xs[k][64 + tx * 4];
#pragma unroll
            for (int j = 0; j < 8; j++) {
                ull b2 = pack2(bb[j], bb[j]);
#pragma unroll
                for (int i = 0; i < 4; i++) acc2[i][j] = ffma2(a2[i], b2, acc2[i][j]);
            }
        }
        __syncthreads();
    }
#pragma unroll
    for (int i = 0; i < 8; i++) {
        int loc  = (i < 4) ? i : (i - 4);
        int i2   = ((i < 4) ? 0 : 2) + (loc >> 1);
        int half = loc & 1;
        int m = bm + ((i < 4) ? 0 : 64) + ty * 4 + loc;
        float bv = bias[m];
        float v[8];
#pragma unroll
        for (int j = 0; j < 8; j++) {
            float2 u = unpack2(acc2[i2][j]);
            v[j] = (half ? u.y : u.x) + bv;
        }
        *(float4*)&C[(size_t)m * N + bn + tx * 4]      = make_float4(v[0], v[1], v[2], v[3]);
        *(float4*)&C[(size_t)m * N + bn + 64 + tx * 4] = make_float4(v[4], v[5], v[6], v[7]);
    }
}

// ---------------- mean over n of q channels (float4) ----------------
__global__ void qmean_k() {
    int b = blockIdx.x >> 8, c = blockIdx.x & 255;
    const float4* p = (const float4*)(g_q + ((size_t)b * DIMC + c) * NQ);
    float s = 0.f;
    for (int n = threadIdx.x; n < 1024; n += 256) {
        float4 v = p[n];
        s += (v.x + v.y) + (v.z + v.w);
    }
    __shared__ float sh[8];
    for (int o = 16; o; o >>= 1) s += __shfl_down_sync(0xffffffffu, s, o);
    if ((threadIdx.x & 31) == 0) sh[threadIdx.x >> 5] = s;
    __syncthreads();
    if (threadIdx.x == 0) {
        float t = 0.f;
#pragma unroll
        for (int i = 0; i < 8; i++) t += sh[i];
        g_qm[b * DIMC + c] = t * (1.0f / NQ);
    }
}

// ---------------- global scores + gumbel ----------------
__global__ void gs_k() {
    int j = blockIdx.x * 128 + threadIdx.x;
    int b = j >> 13, r = j & 8191, h = r >> 10, m = r & 1023;
    const float* qm = g_qm + b * DIMC + h * HD;
    const float* kc = g_kvu + ((size_t)b * 512 + h * 64) * NU + m;
    float s = 0.f;
#pragma unroll
    for (int d = 0; d < 32; d++) s = fmaf(qm[d], kc[(size_t)d * NU], s);

    uint32_t bits;
#if THREEFRY_PARTITIONABLE
    { uint32_t o0, o1; tf2x32(0u, (uint32_t)j, o0, o1); bits = o0 ^ o1; }
#else
    { uint32_t o0, o1;
      if (j < 8192) { tf2x32((uint32_t)j, (uint32_t)(j + 8192), o0, o1); bits = o0; }
      else          { tf2x32((uint32_t)(j - 8192), (uint32_t)j, o0, o1); bits = o1; } }
#endif
    float f = __uint_as_float((bits >> 9) | 0x3f800000u) - 1.0f;
    const float TINY = 1.1754943508222875e-38f;
    float u = fmaxf(TINY, f + TINY);
    float gum = -logf(-logf(u));
    g_gs[j] = s * 0.17677669529663687f + gum;
}

// ---------------- top-4 per (b,h) + 2x2 expansion ----------------
__global__ void topk_k() {
    int bh = blockIdx.x;
    __shared__ float sv[NU];
    __shared__ float rv[256];
    __shared__ int   ri[256];
    __shared__ int   chosen[4];
    int t = threadIdx.x;
    for (int i = t; i < NU; i += 256) sv[i] = g_gs[bh * NU + i];
    __syncthreads();
    for (int rnd = 0; rnd < 4; rnd++) {
        float bestv = -1e30f; int besti = NU;
        for (int i = t; i < NU; i += 256) {
            float v = sv[i];
            if (v > bestv) { bestv = v; besti = i; }
        }
        rv[t] = bestv; ri[t] = besti;
        __syncthreads();
        for (int o = 128; o; o >>= 1) {
            if (t < o) {
                float v2 = rv[t + o]; int i2 = ri[t + o];
                if (v2 > rv[t] || (v2 == rv[t] && i2 < ri[t])) { rv[t] = v2; ri[t] = i2; }
            }
            __syncthreads();
        }
        if (t == 0) { chosen[rnd] = ri[0]; sv[ri[0]] = -1e30f; }
        __syncthreads();
    }
    if (t < 16) {
        int g = t >> 2, kk = t & 3;
        int dh = g >> 1, dw = g & 1;
        int ti = chosen[kk];
        int hi = (ti >> 5) * 2, wi = (ti & 31) * 2;
        g_idx[bh * 16 + t] = (hi + dh) * 64 + (wi + dw);
    }
}

// ---------------- fused coarse + fine attention + gate (f32x2, 1 query/thread) ----------------
__global__ __launch_bounds__(128) void attn_k(const float* __restrict__ Wg,
                                              const float* __restrict__ bg) {
    __shared__ ull Kp[16][128];   // [d-pair][m]  packed K
    __shared__ ull Vp[16][128];
    __shared__ ull FKp[16][16];   // [fine key][d-pair]
    __shared__ ull FVp[16][16];
    __shared__ ull Wgp[32][32];   // [d][c-pair]
    __shared__ float bgs[32];

    int bh = blockIdx.y, b = bh >> 3, h = bh & 7;
    int t = threadIdx.x;
    int n = blockIdx.x * 128 + t;
    const float SCL = 0.17677669529663687f * 1.4426950408889634f;

    for (int e = t; e < 1024; e += 128) ((ull*)Wgp)[e] = ((const ull*)Wg)[e];
    if (t < 32) bgs[t] = bg[t];
    {
        const int* idxp = g_idx + bh * 16;
        const float* fb = g_fkv + ((size_t)b * 512 + h * 64) * NQ;
        for (int e = t; e < 256; e += 128) {
            int j = e >> 4, p = e & 15;
            int nn = idxp[j];
            FKp[j][p] = pack2(fb[(size_t)(2 * p) * NQ + nn],      fb[(size_t)(2 * p + 1) * NQ + nn]);
            FVp[j][p] = pack2(fb[(size_t)(32 + 2 * p) * NQ + nn], fb[(size_t)(33 + 2 * p) * NQ + nn]);
        }
    }

    // load + pre-scale q (packed pairs of adjacent d)
    ull q2[16];
    const float* qb = g_q + ((size_t)b * DIMC + h * HD) * NQ;
#pragma unroll
    for (int p = 0; p < 16; p++)
        q2[p] = pack2(qb[(size_t)(2 * p) * NQ + n] * SCL,
                      qb[(size_t)(2 * p + 1) * NQ + n] * SCL);

    ull acc2[16];
#pragma unroll
    for (int p = 0; p < 16; p++) acc2[p] = 0ull;
    float esum = 0.f;

    const float* kb = g_kvu + ((size_t)b * 512 + h * 64) * NU;
    const float* vb = kb + (size_t)32 * NU;

    for (int m0 = 0; m0 < NU; m0 += 128) {
        __syncthreads();
        for (int e = t; e < 2048; e += 128) {
            int p = e >> 7, m = e & 127;
            Kp[p][m] = pack2(kb[(size_t)(2 * p) * NU + m0 + m], kb[(size_t)(2 * p + 1) * NU + m0 + m]);
            Vp[p][m] = pack2(vb[(size_t)(2 * p) * NU + m0 + m], vb[(size_t)(2 * p + 1) * NU + m0 + m]);
        }
        __syncthreads();
#pragma unroll 1
        for (int m = 0; m < 128; m += 2) {
            ull sa0 = 0ull, sb0 = 0ull, sa1 = 0ull, sb1 = 0ull;
#pragma unroll
            for (int p = 0; p < 16; p += 2) {
                sa0 = ffma2(q2[p],     Kp[p][m],         sa0);
                sb0 = ffma2(q2[p + 1], Kp[p + 1][m],     sb0);
                sa1 = ffma2(q2[p],     Kp[p][m + 1],     sa1);
                sb1 = ffma2(q2[p + 1], Kp[p + 1][m + 1], sb1);
            }
            float2 ua0 = unpack2(sa0), ub0 = unpack2(sb0);
            float2 ua1 = unpack2(sa1), ub1 = unpack2(sb1);
            float s0 = (ua0.x + ua0.y) + (ub0.x + ub0.y);
            float s1 = (ua1.x + ua1.y) + (ub1.x + ub1.y);
            float2 ee = unpack2(fexp2_2(s0, s1));
            esum += ee.x + ee.y;
            ull e20 = pack2(ee.x, ee.x), e21 = pack2(ee.y, ee.y);
#pragma unroll
            for (int p = 0; p < 16; p++) {
                acc2[p] = ffma2(e20, Vp[p][m],     acc2[p]);
                acc2[p] = ffma2(e21, Vp[p][m + 1], acc2[p]);
            }
        }
    }

    // fine attention weights (uses q2, before it is overwritten)
    float fe[16]; float fsum = 0.f;
#pragma unroll
    for (int j = 0; j < 16; j++) {
        ull s2 = 0ull;
#pragma unroll
        for (int p = 0; p < 16; p++) s2 = ffma2(q2[p], FKp[j][p], s2);
        float2 u = unpack2(s2);
        float e1 = fexp2(u.x + u.y);
        fe[j] = e1; fsum += e1;
    }
    ull invf2, invc2;
    { float invf = 1.0f / fsum, invc = 1.0f / esum;
      invf2 = pack2(invf, invf); invc2 = pack2(invc, invc); }

    // refined output overwrites q2; coarse scaled in place in acc2
#pragma unroll
    for (int p = 0; p < 16; p++) {
        ull r = 0ull;
#pragma unroll
        for (int j = 0; j < 16; j++) r = ffma2(pack2(fe[j], fe[j]), FVp[j][p], r);
        q2[p]   = fmul2(r, invf2);
        acc2[p] = fmul2(acc2[p], invc2);
    }

    // gate + output
    float* outb = g_out + ((size_t)b * DIMC + h * HD) * NQ + n;
#pragma unroll
    for (int d = 0; d < 32; d++) {
        ull g2 = 0ull;
#pragma unroll
        for (int p = 0; p < 16; p++) {
            g2 = ffma2(acc2[p], Wgp[d][p],      g2);
            g2 = ffma2(q2[p],   Wgp[d][16 + p], g2);
        }
        float2 u = unpack2(g2);
        float s = u.x + u.y + bgs[d];
        float gate = 1.0f / (1.0f + fexp2(-s * 1.4426950408889634f));
        float2 cc = unpack2(acc2[d >> 1]);
        float2 rr = unpack2(q2[d >> 1]);
        float cd = (d & 1) ? cc.y : cc.x;
        float rd = (d & 1) ? rr.y : rr.x;
        outb[(size_t)d * NQ] = cd + gate * (rd - cd);
    }
}

// ---------------- depthwise 7x7 conv on v (32x32 grid) ----------------
__global__ void pe_conv_k(const float* __restrict__ Wpe, const float* __restrict__ bpe) {
    int gid = blockIdx.x * 128 + threadIdx.x;
    int p = gid & 1023, c = (gid >> 10) & 255, b = gid >> 18;
    int y = p >> 5, x = p & 31;
    int h = c >> 5, d = c & 31;
    const float* vsrc = g_kvu + ((size_t)b * 512 + h * 64 + 32 + d) * NU;
    const float* w = Wpe + c * 49;
    float s = bpe[c];
#pragma unroll
    for (int ky = 0; ky < 7; ky++) {
        int iy = y + ky - 3;
        if ((unsigned)iy < 32u) {
#pragma unroll
            for (int kx = 0; kx < 7; kx++) {
                int ix = x + kx - 3;
                if ((unsigned)ix < 32u) s = fmaf(vsrc[iy * 32 + ix], w[ky * 7 + kx], s);
            }
        }
    }
    g_vpe[gid] = s;
}

// ---------------- bilinear 2x upsample + add ----------------
__global__ void upadd_k() {
    int gid = blockIdx.x * 256 + threadIdx.x;
    int n = gid & 4095, c = (gid >> 12) & 255, b = gid >> 20;
    int y = n >> 6, x = n & 63;
    float fy = (y + 0.5f) * 0.5f - 0.5f;
    float fx = (x + 0.5f) * 0.5f - 0.5f;
    float yf = floorf(fy), xf = floorf(fx);
    float ty = fy - yf, tx = fx - xf;
    int y0 = max(0, min(31, (int)yf)),     y1 = max(0, min(31, (int)yf + 1));
    int x0 = max(0, min(31, (int)xf)),     x1 = max(0, min(31, (int)xf + 1));
    const float* src = g_vpe + ((size_t)b * 256 + c) * NU;
    float v = (1.f - ty) * ((1.f - tx) * src[y0 * 32 + x0] + tx * src[y0 * 32 + x1])
            +        ty  * ((1.f - tx) * src[y1 * 32 + x0] + tx * src[y1 * 32 + x1]);
    g_out[gid] += v;
}

// ---------------- launch ----------------
extern "C" void kernel_launch(void* const* d_in, const int* in_sizes, int n_in,
                              void* d_out, int out_size) {
    const float* x     = (const float*)d_in[0];
    const float* uf    = (const float*)d_in[1];
    const float* Wq    = (const float*)d_in[2];
    const float* bq    = (const float*)d_in[3];
    const float* Wkv   = (const float*)d_in[4];
    const float* bkv   = (const float*)d_in[5];
    const float* Wproj = (const float*)d_in[6];
    const float* bproj = (const float*)d_in[7];
    const float* Wpe   = (const float*)d_in[8];
    const float* bpe   = (const float*)d_in[9];
    const float* Wg    = (const float*)d_in[10];
    const float* bg    = (const float*)d_in[11];
    float* out = (float*)d_out;

    float *pq, *pkvu, *pfkv, *pout;
    cudaGetSymbolAddress((void**)&pq,   g_q);
    cudaGetSymbolAddress((void**)&pkvu, g_kvu);
    cudaGetSymbolAddress((void**)&pfkv, g_fkv);
    cudaGetSymbolAddress((void**)&pout, g_out);

    gemm128<<<dim3(32, 2, 2), 256>>>(Wq,  x,  bq,  pq,   256, 4096);
    gemm128<<<dim3(8,  4, 2), 256>>>(Wkv, uf, bkv, pkvu, 512, 1024);
    gemm128<<<dim3(32, 4, 2), 256>>>(Wkv, x,  bkv, pfkv, 512, 4096);
    qmean_k<<<512, 256>>>();
    gs_k<<<128, 128>>>();
    topk_k<<<16, 256>>>();
    attn_k<<<dim3(32, 16), 128>>>(Wg, bg);
    pe_conv_k<<<4096, 128>>>(Wpe, bpe);
    upadd_k<<<8192, 256>>>();
    gemm128<<<dim3(32, 2, 2), 256>>>(Wproj, pout, bproj, out, 256, 4096);
}